// round 1
// baseline (speedup 1.0000x reference)
#include <cuda_runtime.h>

// out[b,c,h,w] = max over 4 directional 3x3 Laplacians (zero-padded):
//   lap0 = x[h,w-1] + x[h,w+1] - 2x
//   lap1 = x[h-1,w] + x[h+1,w] - 2x
//   lap2 = x[h-1,w+1] + x[h+1,w-1] - 2x
//   lap3 = x[h-1,w-1] + x[h+1,w+1] - 2x

#define W 512
#define H 512
#define RPT 4   // rows per thread

// Load a 6-wide window [w0-1 .. w0+4] of row h into a[0..5], zero-padded.
__device__ __forceinline__ void load_row6(const float* __restrict__ img,
                                          int h, int w0, float a[6]) {
    if (h < 0 || h >= H) {
        #pragma unroll
        for (int i = 0; i < 6; i++) a[i] = 0.f;
        return;
    }
    const float* row = img + h * W;
    float4 v = __ldg((const float4*)(row + w0));
    a[1] = v.x; a[2] = v.y; a[3] = v.z; a[4] = v.w;
    a[0] = (w0 > 0)       ? __ldg(row + w0 - 1) : 0.f;
    a[5] = (w0 + 4 < W)   ? __ldg(row + w0 + 4) : 0.f;
}

__global__ __launch_bounds__(128, 8)
void maxlap_kernel(const float* __restrict__ x, float* __restrict__ out) {
    // blockIdx.y = image index (b*c), blockIdx.x = row-group, threadIdx.x covers full width
    const int img = blockIdx.y;
    const int h0  = blockIdx.x * RPT;
    const int w0  = threadIdx.x * 4;

    const float* in  = x   + (size_t)img * H * W;
    float*       dst = out + (size_t)img * H * W;

    float t[6], m[6], b[6];
    load_row6(in, h0 - 1, w0, t);
    load_row6(in, h0,     w0, m);

    #pragma unroll
    for (int rr = 0; rr < RPT; rr++) {
        const int h = h0 + rr;
        load_row6(in, h + 1, w0, b);

        float4 o;
        float* op = (float*)&o;
        #pragma unroll
        for (int i = 0; i < 4; i++) {
            const float c  = m[i + 1];
            const float c2 = c + c;
            const float lap0 = (m[i]     + m[i + 2]) - c2;  // horizontal
            const float lap1 = (t[i + 1] + b[i + 1]) - c2;  // vertical
            const float lap2 = (t[i + 2] + b[i])     - c2;  // anti-diagonal
            const float lap3 = (t[i]     + b[i + 2]) - c2;  // diagonal
            op[i] = fmaxf(fmaxf(lap0, lap1), fmaxf(lap2, lap3));
        }
        *(float4*)(dst + h * W + w0) = o;

        // roll window
        #pragma unroll
        for (int i = 0; i < 6; i++) { t[i] = m[i]; m[i] = b[i]; }
    }
}

extern "C" void kernel_launch(void* const* d_in, const int* in_sizes, int n_in,
                              void* d_out, int out_size) {
    const float* x = (const float*)d_in[0];
    float* out = (float*)d_out;

    const int n_img = in_sizes[0] / (H * W);  // B*C = 48

    dim3 block(W / 4);                // 128 threads, full row width
    dim3 grid(H / RPT, n_img);        // 128 x 48
    maxlap_kernel<<<grid, block>>>(x, out);
}

// round 2
// speedup vs baseline: 1.0135x; 1.0135x over previous
#include <cuda_runtime.h>

// out[b,c,h,w] = max over 4 directional 3x3 Laplacians (zero-padded):
//   lap0 = x[h,w-1] + x[h,w+1] - 2x      (horizontal)
//   lap1 = x[h-1,w] + x[h+1,w] - 2x      (vertical)
//   lap2 = x[h-1,w+1] + x[h+1,w-1] - 2x  (anti-diagonal)
//   lap3 = x[h-1,w-1] + x[h+1,w+1] - 2x  (diagonal)

#define W 512
#define H 512
#define RPT 8   // rows per thread

// Load a 6-wide window [w0-1 .. w0+4] of row h into a[0..5], zero-padded.
// Halo elements come from warp shuffles; only lanes 0/31 touch memory for them.
__device__ __forceinline__ void load_row6(const float* __restrict__ img,
                                          int h, int w0, int lane, float a[6]) {
    if (h < 0 || h >= H) {
        #pragma unroll
        for (int i = 0; i < 6; i++) a[i] = 0.f;
        return;
    }
    const float* row = img + h * W;
    float4 v = __ldg((const float4*)(row + w0));
    a[1] = v.x; a[2] = v.y; a[3] = v.z; a[4] = v.w;

    float l = __shfl_up_sync(0xffffffffu, v.w, 1);    // lane-1's w  = x[w0-1]
    float r = __shfl_down_sync(0xffffffffu, v.x, 1);  // lane+1's x  = x[w0+4]
    if (lane == 0)  l = (w0 > 0)     ? __ldg(row + w0 - 1) : 0.f;
    if (lane == 31) r = (w0 + 4 < W) ? __ldg(row + w0 + 4) : 0.f;
    a[0] = l;
    a[5] = r;
}

__global__ __launch_bounds__(128, 12)
void maxlap_kernel(const float* __restrict__ x, float* __restrict__ out) {
    const int img  = blockIdx.y;
    const int h0   = blockIdx.x * RPT;
    const int w0   = threadIdx.x * 4;
    const int lane = threadIdx.x & 31;

    const float* in  = x   + (size_t)img * H * W;
    float*       dst = out + (size_t)img * H * W;

    float t[6], m[6], b[6];
    load_row6(in, h0 - 1, w0, lane, t);
    load_row6(in, h0,     w0, lane, m);

    #pragma unroll
    for (int rr = 0; rr < RPT; rr++) {
        const int h = h0 + rr;
        load_row6(in, h + 1, w0, lane, b);

        float4 o;
        float* op = (float*)&o;
        #pragma unroll
        for (int i = 0; i < 4; i++) {
            const float c  = m[i + 1];
            const float c2 = c + c;
            const float lap0 = (m[i]     + m[i + 2]) - c2;
            const float lap1 = (t[i + 1] + b[i + 1]) - c2;
            const float lap2 = (t[i + 2] + b[i])     - c2;
            const float lap3 = (t[i]     + b[i + 2]) - c2;
            op[i] = fmaxf(fmaxf(lap0, lap1), fmaxf(lap2, lap3));
        }
        *(float4*)(dst + h * W + w0) = o;

        #pragma unroll
        for (int i = 0; i < 6; i++) { t[i] = m[i]; m[i] = b[i]; }
    }
}

extern "C" void kernel_launch(void* const* d_in, const int* in_sizes, int n_in,
                              void* d_out, int out_size) {
    const float* x = (const float*)d_in[0];
    float* out = (float*)d_out;

    const int n_img = in_sizes[0] / (H * W);  // B*C = 48

    dim3 block(W / 4);                 // 128 threads, full row width
    dim3 grid(H / RPT, n_img);         // 64 x 48 = 3072 blocks
    maxlap_kernel<<<grid, block>>>(x, out);
}